// round 1
// baseline (speedup 1.0000x reference)
#include <cuda_runtime.h>
#include <cstddef>

#define B_ 4
#define T_ 1024
#define D_ 512
#define H_ 16
#define DH_ 32
#define BT_ (B_ * T_)

// ---- scratch (static device globals; no runtime allocation) ----
__device__ float g_qh[BT_ * D_];    // 8 MB
__device__ float g_kh[BT_ * D_];
__device__ float g_vh[BT_ * D_];
__device__ float g_ph[BT_ * D_];
__device__ float g_ctx[BT_ * D_];
__device__ float g_P[(size_t)B_ * H_ * T_ * T_];  // 256 MB, unshifted pos scores
__device__ float g_S[(size_t)B_ * H_ * T_ * T_];  // 256 MB, scores -> attn (in place)

// =====================================================================
// GEMM: C[M x 512] = A[M x 512] @ W[512 x 512] (+ bias), M = 4096.
// Tile 64x64, BK=16, 256 threads, 4x4 per thread.
// sel: 0..3 -> C is g_qh/g_kh/g_vh/g_ph ; 4 -> A is g_ctx, C is Cext.
// =====================================================================
__global__ __launch_bounds__(256) void gemm512_kernel(
    const float* __restrict__ Aext, const float* __restrict__ W,
    const float* __restrict__ bias, float* __restrict__ Cext, int sel) {
  const float* A = (sel == 4) ? g_ctx : Aext;
  float* C = (sel == 0) ? g_qh : (sel == 1) ? g_kh : (sel == 2) ? g_vh
           : (sel == 3) ? g_ph : Cext;

  __shared__ float As[16][68];   // [k][m], pad keeps 16B alignment (68*4=272=17*16)
  __shared__ float Bs[16][64];   // [k][n]

  const int tid = threadIdx.x;
  const int tx = tid & 15, ty = tid >> 4;
  const int m0 = blockIdx.y * 64, n0 = blockIdx.x * 64;
  const int lr = tid >> 2, lcs = (tid & 3) * 4;      // A tile loader
  const int lkr = tid >> 4, lnc = (tid & 15) * 4;    // W tile loader

  float acc[4][4] = {};

  for (int k0 = 0; k0 < 512; k0 += 16) {
    float4 a4 = *reinterpret_cast<const float4*>(&A[(size_t)(m0 + lr) * 512 + k0 + lcs]);
    float4 b4 = *reinterpret_cast<const float4*>(&W[(size_t)(k0 + lkr) * 512 + n0 + lnc]);
    As[lcs + 0][lr] = a4.x; As[lcs + 1][lr] = a4.y;
    As[lcs + 2][lr] = a4.z; As[lcs + 3][lr] = a4.w;
    *reinterpret_cast<float4*>(&Bs[lkr][lnc]) = b4;
    __syncthreads();
#pragma unroll
    for (int kk = 0; kk < 16; kk++) {
      float4 a = *reinterpret_cast<const float4*>(&As[kk][ty * 4]);
      float4 b = *reinterpret_cast<const float4*>(&Bs[kk][tx * 4]);
      float av[4] = {a.x, a.y, a.z, a.w};
      float bv[4] = {b.x, b.y, b.z, b.w};
#pragma unroll
      for (int i = 0; i < 4; i++)
#pragma unroll
        for (int j = 0; j < 4; j++) acc[i][j] += av[i] * bv[j];
    }
    __syncthreads();
  }

  float4 bb = make_float4(0.f, 0.f, 0.f, 0.f);
  if (bias) bb = *reinterpret_cast<const float4*>(&bias[n0 + tx * 4]);
#pragma unroll
  for (int i = 0; i < 4; i++) {
    float4 o;
    o.x = acc[i][0] + bb.x; o.y = acc[i][1] + bb.y;
    o.z = acc[i][2] + bb.z; o.w = acc[i][3] + bb.w;
    *reinterpret_cast<float4*>(&C[(size_t)(m0 + ty * 4 + i) * 512 + n0 + tx * 4]) = o;
  }
}

// =====================================================================
// Pos score GEMM: P[bh, t, j] = sum_d (qh[b,t,h,d] + v_bias[h,d]) * ph[b,j,h,d]
// One 64x64 tile per block, K = 32 (single tile, no K loop).
// =====================================================================
__global__ __launch_bounds__(256) void pscore_kernel(const float* __restrict__ vbias) {
  __shared__ float As[32][68];  // [k][t]
  __shared__ float Bs[32][68];  // [k][j]
  const int tid = threadIdx.x;
  const int bz = blockIdx.z, b = bz >> 4, h = bz & 15;
  const int t0 = blockIdx.y * 64, j0 = blockIdx.x * 64;

  const int e0 = tid * 2;
#pragma unroll
  for (int e = e0; e < e0 + 2; e++) {
    const int r = e >> 3, seg = (e & 7) * 4;
    float4 a4 = *reinterpret_cast<const float4*>(
        &g_qh[(size_t)(b * T_ + t0 + r) * D_ + h * DH_ + seg]);
    float4 vbv = *reinterpret_cast<const float4*>(&vbias[h * DH_ + seg]);
    float4 b4 = *reinterpret_cast<const float4*>(
        &g_ph[(size_t)(b * T_ + j0 + r) * D_ + h * DH_ + seg]);
    As[seg + 0][r] = a4.x + vbv.x; As[seg + 1][r] = a4.y + vbv.y;
    As[seg + 2][r] = a4.z + vbv.z; As[seg + 3][r] = a4.w + vbv.w;
    Bs[seg + 0][r] = b4.x; Bs[seg + 1][r] = b4.y;
    Bs[seg + 2][r] = b4.z; Bs[seg + 3][r] = b4.w;
  }
  __syncthreads();

  const int tx = tid & 15, ty = tid >> 4;
  float acc[4][4] = {};
#pragma unroll
  for (int kk = 0; kk < 32; kk++) {
    float4 a = *reinterpret_cast<const float4*>(&As[kk][ty * 4]);
    float4 b = *reinterpret_cast<const float4*>(&Bs[kk][tx * 4]);
    float av[4] = {a.x, a.y, a.z, a.w};
    float bv[4] = {b.x, b.y, b.z, b.w};
#pragma unroll
    for (int i = 0; i < 4; i++)
#pragma unroll
      for (int j = 0; j < 4; j++) acc[i][j] += av[i] * bv[j];
  }

#pragma unroll
  for (int i = 0; i < 4; i++) {
    const int t = t0 + ty * 4 + i;
    float4 o = make_float4(acc[i][0], acc[i][1], acc[i][2], acc[i][3]);
    *reinterpret_cast<float4*>(&g_P[((size_t)bz * T_ + t) * T_ + j0 + tx * 4]) = o;
  }
}

// =====================================================================
// Content score GEMM + relative-shift combine:
// S[bh,t,s] = ( (qh+u_bias)·kh  +  shift(P)[t,s] ) / sqrt(512)
// shift(P)[t,s] = P[t, s-t+T-1]   if s <= t
//              = 0                if s == t+1
//              = P[t+1, s-t-2]    if s >= t+2      (coalesced: j = s + const)
// =====================================================================
__global__ __launch_bounds__(256) void cscore_kernel(const float* __restrict__ ubias) {
  __shared__ float As[32][68];
  __shared__ float Bs[32][68];
  const int tid = threadIdx.x;
  const int bz = blockIdx.z, b = bz >> 4, h = bz & 15;
  const int t0 = blockIdx.y * 64, s0 = blockIdx.x * 64;

  const int e0 = tid * 2;
#pragma unroll
  for (int e = e0; e < e0 + 2; e++) {
    const int r = e >> 3, seg = (e & 7) * 4;
    float4 a4 = *reinterpret_cast<const float4*>(
        &g_qh[(size_t)(b * T_ + t0 + r) * D_ + h * DH_ + seg]);
    float4 ubv = *reinterpret_cast<const float4*>(&ubias[h * DH_ + seg]);
    float4 b4 = *reinterpret_cast<const float4*>(
        &g_kh[(size_t)(b * T_ + s0 + r) * D_ + h * DH_ + seg]);
    As[seg + 0][r] = a4.x + ubv.x; As[seg + 1][r] = a4.y + ubv.y;
    As[seg + 2][r] = a4.z + ubv.z; As[seg + 3][r] = a4.w + ubv.w;
    Bs[seg + 0][r] = b4.x; Bs[seg + 1][r] = b4.y;
    Bs[seg + 2][r] = b4.z; Bs[seg + 3][r] = b4.w;
  }
  __syncthreads();

  const int tx = tid & 15, ty = tid >> 4;
  float acc[4][4] = {};
#pragma unroll
  for (int kk = 0; kk < 32; kk++) {
    float4 a = *reinterpret_cast<const float4*>(&As[kk][ty * 4]);
    float4 b = *reinterpret_cast<const float4*>(&Bs[kk][tx * 4]);
    float av[4] = {a.x, a.y, a.z, a.w};
    float bv[4] = {b.x, b.y, b.z, b.w};
#pragma unroll
    for (int i = 0; i < 4; i++)
#pragma unroll
      for (int j = 0; j < 4; j++) acc[i][j] += av[i] * bv[j];
  }

  const float inv_sqrt_d = 0.04419417382415922f;  // 1/sqrt(512)
#pragma unroll
  for (int i = 0; i < 4; i++) {
    const int t = t0 + ty * 4 + i;
    const size_t rowb = ((size_t)bz * T_ + t) * T_;
#pragma unroll
    for (int j = 0; j < 4; j++) {
      const int s = s0 + tx * 4 + j;
      float pv;
      if (s <= t)            pv = g_P[rowb + (s - t + (T_ - 1))];
      else if (s == t + 1)   pv = 0.f;
      else                   pv = g_P[rowb + T_ + (s - t - 2)];  // row t+1 (t<=1021 here)
      g_S[rowb + s] = (acc[i][j] + pv) * inv_sqrt_d;
    }
  }
}

// =====================================================================
// Row softmax over 1024 elements, in place on g_S. One block per row.
// =====================================================================
__global__ __launch_bounds__(256) void softmax_kernel() {
  const size_t row = blockIdx.x;
  float* p = g_S + row * (size_t)T_;
  const int tid = threadIdx.x;
  __shared__ float red[8];

  float4 x = *reinterpret_cast<float4*>(&p[tid * 4]);
  float m = fmaxf(fmaxf(x.x, x.y), fmaxf(x.z, x.w));
#pragma unroll
  for (int o = 16; o > 0; o >>= 1) m = fmaxf(m, __shfl_xor_sync(0xffffffffu, m, o));
  if ((tid & 31) == 0) red[tid >> 5] = m;
  __syncthreads();
  if (tid == 0) {
    float mm = red[0];
#pragma unroll
    for (int i = 1; i < 8; i++) mm = fmaxf(mm, red[i]);
    red[0] = mm;
  }
  __syncthreads();
  m = red[0];
  __syncthreads();

  x.x = __expf(x.x - m); x.y = __expf(x.y - m);
  x.z = __expf(x.z - m); x.w = __expf(x.w - m);
  float s = (x.x + x.y) + (x.z + x.w);
#pragma unroll
  for (int o = 16; o > 0; o >>= 1) s += __shfl_xor_sync(0xffffffffu, s, o);
  if ((tid & 31) == 0) red[tid >> 5] = s;
  __syncthreads();
  if (tid == 0) {
    float ss = 0.f;
#pragma unroll
    for (int i = 0; i < 8; i++) ss += red[i];
    red[0] = ss;
  }
  __syncthreads();
  const float r = 1.0f / red[0];

  x.x *= r; x.y *= r; x.z *= r; x.w *= r;
  *reinterpret_cast<float4*>(&p[tid * 4]) = x;
}

// =====================================================================
// Attn @ V: ctx[b, t, h*32+dh] = sum_s S[bh,t,s] * vh[b,s,h,dh]
// Block: 64 t-rows x 32 dh for one (b,h); 256 threads = (32 dh, 8 t-groups).
// =====================================================================
__global__ __launch_bounds__(256) void av_kernel() {
  __shared__ float Ss[64][33];
  __shared__ float Vs[32][33];
  const int tid = threadIdx.x;
  const int bz = blockIdx.y, b = bz >> 4, h = bz & 15;
  const int t0 = blockIdx.x * 64;
  const int dh = tid & 31, tg = tid >> 5;

  const size_t Srow0 = ((size_t)bz * T_ + t0) * T_;
  float acc[8] = {};

  for (int s0 = 0; s0 < T_; s0 += 32) {
    {
      const int t = tid >> 2, soff = (tid & 3) * 8;
      float4 sa = *reinterpret_cast<const float4*>(&g_S[Srow0 + (size_t)t * T_ + s0 + soff]);
      float4 sb = *reinterpret_cast<const float4*>(&g_S[Srow0 + (size_t)t * T_ + s0 + soff + 4]);
      Ss[t][soff + 0] = sa.x; Ss[t][soff + 1] = sa.y;
      Ss[t][soff + 2] = sa.z; Ss[t][soff + 3] = sa.w;
      Ss[t][soff + 4] = sb.x; Ss[t][soff + 5] = sb.y;
      Ss[t][soff + 6] = sb.z; Ss[t][soff + 7] = sb.w;
      const int vr = tid >> 3, vseg = (tid & 7) * 4;
      float4 v4 = *reinterpret_cast<const float4*>(
          &g_vh[(size_t)(b * T_ + s0 + vr) * D_ + h * DH_ + vseg]);
      Vs[vr][vseg + 0] = v4.x; Vs[vr][vseg + 1] = v4.y;
      Vs[vr][vseg + 2] = v4.z; Vs[vr][vseg + 3] = v4.w;
    }
    __syncthreads();
#pragma unroll
    for (int ss = 0; ss < 32; ss++) {
      const float vv = Vs[ss][dh];
#pragma unroll
      for (int i = 0; i < 8; i++) acc[i] += Ss[tg * 8 + i][ss] * vv;
    }
    __syncthreads();
  }

#pragma unroll
  for (int i = 0; i < 8; i++)
    g_ctx[(size_t)(b * T_ + t0 + tg * 8 + i) * D_ + h * DH_ + dh] = acc[i];
}

// =====================================================================
extern "C" void kernel_launch(void* const* d_in, const int* in_sizes, int n_in,
                              void* d_out, int out_size) {
  const float* q   = (const float*)d_in[0];
  const float* k   = (const float*)d_in[1];
  const float* v   = (const float*)d_in[2];
  const float* pos = (const float*)d_in[3];
  const float* Wq  = (const float*)d_in[4];
  const float* bq  = (const float*)d_in[5];
  const float* Wp  = (const float*)d_in[6];
  const float* Wf  = (const float*)d_in[7];
  const float* bf  = (const float*)d_in[8];
  const float* ub  = (const float*)d_in[9];
  const float* vb  = (const float*)d_in[10];
  float* out = (float*)d_out;

  dim3 gg(8, 64);  // 512/64 cols, 4096/64 rows
  gemm512_kernel<<<gg, 256>>>(q,   Wq, bq,      nullptr, 0);  // qh
  gemm512_kernel<<<gg, 256>>>(k,   Wq, bq,      nullptr, 1);  // kh
  gemm512_kernel<<<gg, 256>>>(v,   Wq, bq,      nullptr, 2);  // vh
  gemm512_kernel<<<gg, 256>>>(pos, Wp, nullptr, nullptr, 3);  // ph

  dim3 gs(16, 16, 64);  // (s/j tiles, t tiles, b*h)
  pscore_kernel<<<gs, 256>>>(vb);
  cscore_kernel<<<gs, 256>>>(ub);

  softmax_kernel<<<B_ * H_ * T_, 256>>>();

  av_kernel<<<dim3(16, 64), 256>>>();

  gemm512_kernel<<<gg, 256>>>(nullptr, Wf, bf, out, 4);  // final projection
}